// round 2
// baseline (speedup 1.0000x reference)
#include <cuda_runtime.h>
#include <cuda_bf16.h>

// SepConv: out[b,c,i,j] = sum_{u,v} img[b,c,i+u,j+v] * vert[b,u,i,j] * hori[b,v,i,j]
// Shapes: img[8,3,512,512], hori[8,13,500,500], vert[8,13,500,500], out[8,3,500,500]
// Factorized: out = sum_u vert[u] * (sum_v hori[v] * img[i+u, j+v])
// R2: 8-wide j per thread (was 4) -> 1.6x fewer shared-memory bytes per output.

#define KSZ 13
#define CC  3
#define WW  512
#define HH  512
#define WO  500
#define HO  500

#define TXN 16                     // thread-groups in j; each thread covers 8 j
#define TY  8                      // output rows per block
#define JW  8
#define JBLK (TXN * JW)            // 128 output columns per block
#define TILE_ROWS (TY + KSZ - 1)   // 20 img rows
#define TILE_Q   36                // float4 per tile row (144 floats >= 128+19)

__global__ __launch_bounds__(TXN * TY, 2)
void sepconv_kernel(const float* __restrict__ img,
                    const float* __restrict__ hori,
                    const float* __restrict__ vert,
                    float* __restrict__ out) {
    __shared__ float4 s[CC][TILE_ROWS][TILE_Q];

    const int b  = blockIdx.z;
    const int j0 = blockIdx.x * JBLK;
    const int i0 = blockIdx.y * TY;
    const int tx = threadIdx.x, ty = threadIdx.y;
    const int tid = ty * TXN + tx;

    // ---- cooperative load of the img tile (3 channels, 20 rows, 144 cols) ----
    const int NQ = CC * TILE_ROWS * TILE_Q;   // 2160 float4
    for (int f = tid; f < NQ; f += TXN * TY) {
        int c   = f / (TILE_ROWS * TILE_Q);
        int rem = f - c * (TILE_ROWS * TILE_Q);
        int r   = rem / TILE_Q;
        int q   = rem - r * TILE_Q;
        int gx  = i0 + r; if (gx > WW - 1) gx = WW - 1;   // clamped rows feed only invalid outputs
        int gy  = j0 + 4 * q;
        const float* base = img + (((size_t)b * CC + c) * WW + gx) * HH;
        float4 val;
        if (gy + 3 <= HH - 1) {
            val = *(const float4*)(base + gy);
        } else {
            int y0 = gy     < HH ? gy     : HH - 1;
            int y1 = gy + 1 < HH ? gy + 1 : HH - 1;
            int y2 = gy + 2 < HH ? gy + 2 : HH - 1;
            int y3 = gy + 3 < HH ? gy + 3 : HH - 1;
            val = make_float4(base[y0], base[y1], base[y2], base[y3]);
        }
        s[c][r][q] = val;
    }
    __syncthreads();

    const int i = i0 + ty;
    const int j = j0 + JW * tx;
    if (i >= WO || j >= HO) return;              // no further barriers below
    const bool hiv = (j + JW - 1) < HO;          // second float4 (j+4..j+7) fully valid?

    // ---- per-pixel horizontal weights in registers (13 x 2 float4) ----
    float4 hwa[KSZ], hwb[KSZ];
    const float* hbase = hori + (((size_t)b * KSZ) * WO + i) * HO + j;
    #pragma unroll
    for (int v = 0; v < KSZ; v++) {
        const float* p = hbase + (size_t)v * WO * HO;
        hwa[v] = *(const float4*)p;
        hwb[v] = hiv ? *(const float4*)(p + 4) : make_float4(0.f, 0.f, 0.f, 0.f);
    }

    float4 accA[CC], accB[CC];
    #pragma unroll
    for (int c = 0; c < CC; c++) {
        accA[c] = make_float4(0.f, 0.f, 0.f, 0.f);
        accB[c] = make_float4(0.f, 0.f, 0.f, 0.f);
    }

    const float* vbase = vert + (((size_t)b * KSZ) * WO + i) * HO + j;

    #pragma unroll
    for (int u = 0; u < KSZ; u++) {
        const float* vp = vbase + (size_t)u * WO * HO;
        float4 vwa = *(const float4*)vp;
        float4 vwb = hiv ? *(const float4*)(vp + 4) : make_float4(0.f, 0.f, 0.f, 0.f);

        #pragma unroll
        for (int c = 0; c < CC; c++) {
            // 20-float register window: columns j .. j+19 of img row i+u
            const float4* rowp = &s[c][ty + u][0] + 2 * tx;
            float w[JW + KSZ - 1 + 1];   // 20 used (pad to keep indexing simple)
            #pragma unroll
            for (int k = 0; k < 5; k++) {
                float4 t4 = rowp[k];
                w[4*k+0] = t4.x; w[4*k+1] = t4.y; w[4*k+2] = t4.z; w[4*k+3] = t4.w;
            }
            float r0 = 0.f, r1 = 0.f, r2 = 0.f, r3 = 0.f;
            float r4 = 0.f, r5 = 0.f, r6 = 0.f, r7 = 0.f;
            #pragma unroll
            for (int v = 0; v < KSZ; v++) {
                r0 = fmaf(hwa[v].x, w[v + 0], r0);
                r1 = fmaf(hwa[v].y, w[v + 1], r1);
                r2 = fmaf(hwa[v].z, w[v + 2], r2);
                r3 = fmaf(hwa[v].w, w[v + 3], r3);
                r4 = fmaf(hwb[v].x, w[v + 4], r4);
                r5 = fmaf(hwb[v].y, w[v + 5], r5);
                r6 = fmaf(hwb[v].z, w[v + 6], r6);
                r7 = fmaf(hwb[v].w, w[v + 7], r7);
            }
            accA[c].x = fmaf(vwa.x, r0, accA[c].x);
            accA[c].y = fmaf(vwa.y, r1, accA[c].y);
            accA[c].z = fmaf(vwa.z, r2, accA[c].z);
            accA[c].w = fmaf(vwa.w, r3, accA[c].w);
            accB[c].x = fmaf(vwb.x, r4, accB[c].x);
            accB[c].y = fmaf(vwb.y, r5, accB[c].y);
            accB[c].z = fmaf(vwb.z, r6, accB[c].z);
            accB[c].w = fmaf(vwb.w, r7, accB[c].w);
        }
    }

    #pragma unroll
    for (int c = 0; c < CC; c++) {
        float* obase = out + (((size_t)b * CC + c) * WO + i) * HO + j;
        *(float4*)obase = accA[c];
        if (hiv) *(float4*)(obase + 4) = accB[c];
    }
}

extern "C" void kernel_launch(void* const* d_in, const int* in_sizes, int n_in,
                              void* d_out, int out_size) {
    const float* img  = (const float*)d_in[0];
    const float* hori = (const float*)d_in[1];
    const float* vert = (const float*)d_in[2];
    float* out = (float*)d_out;

    const int B = 8;
    dim3 block(TXN, TY);                    // 128 threads
    dim3 grid((HO + JBLK - 1) / JBLK,       // 4
              (WO + TY - 1) / TY,           // 63
              B);                           // 8
    sepconv_kernel<<<grid, block>>>(img, hori, vert, out);
}